// round 10
// baseline (speedup 1.0000x reference)
#include <cuda_runtime.h>
#include <cstdint>
#include <cstddef>

// Problem constants (fixed by setup_inputs)
#define NN 4
#define H0 60
#define W0 80
#define H1 60
#define W1 80
#define LL (H0*W0)     // 4800 rows
#define SS (H1*W1)     // 4800 cols
#define NL (NN*LL)
#define THRV 0.2f
#define BR 2

#define TPBC 512           // consumer threads
#define TPB  544           // +1 producer warp
#define NW (TPBC/32)       // 16 consumer warps
#define NQ (SS/4)          // 1200 float4 per row
#define ROWB (SS*4)        // 19200 bytes per row
#define RPS 2              // rows per pipeline stage
#define STAGEB (RPS*ROWB)  // 38400
#define DEPTH 5            // pipeline stages (10 rows in flight)
#define CTAS_PER_N 37      // 37*4 = 148 CTAs = 1 per SM
#define MAXROWS 130        // ceil(4800/37)
#define TAILQ (NQ - 2*TPBC) // 176: threads with a 3rd float4

// smem layout (dynamic)
#define SM_TILES 0                          // DEPTH*STAGEB = 192000
#define SM_PMAX  (DEPTH*STAGEB)             // 192000
#define SM_PCNT  (SM_PMAX + MAXROWS*NW*4)   // 200320
#define SM_PIDX  (SM_PCNT + MAXROWS*NW*4)   // 208640
#define SM_MBAR  (SM_PIDX + MAXROWS*NW*4)   // 216960: full[5] then empty[5]
#define SMEM_REQ 217088

// Scratch (no allocations allowed). All of it is plain-stored every run before
// being read -> no init requirements, fully deterministic.
__device__ float    g_colpart[(size_t)CTAS_PER_N*NN*SS];  // per-CTA colmax partials, 2.84 MB
__device__ float    g_rowmax[NL];
__device__ int      g_rowj[NL];          // min index achieving rowmax
__device__ int      g_rowcnt[NL];        // count of elements == rowmax

__device__ __forceinline__ uint32_t smem_u32(const void* p) {
    uint32_t a;
    asm("{ .reg .u64 t; cvta.to.shared.u64 t, %1; cvt.u32.u64 %0, t; }" : "=r"(a) : "l"(p));
    return a;
}
__device__ __forceinline__ void mbar_init(uint32_t m, uint32_t cnt) {
    asm volatile("mbarrier.init.shared.b64 [%0], %1;" :: "r"(m), "r"(cnt) : "memory");
}
__device__ __forceinline__ void mbar_expect_tx(uint32_t m, uint32_t bytes) {
    asm volatile("mbarrier.arrive.expect_tx.shared.b64 _, [%0], %1;" :: "r"(m), "r"(bytes) : "memory");
}
__device__ __forceinline__ void mbar_arrive(uint32_t m) {
    asm volatile("mbarrier.arrive.shared.b64 _, [%0];" :: "r"(m) : "memory");
}
__device__ __forceinline__ void bulk_ldg(uint32_t dst, const void* src, uint32_t bytes, uint32_t mbar) {
    asm volatile("cp.async.bulk.shared::cluster.global.mbarrier::complete_tx::bytes [%0], [%1], %2, [%3];"
                 :: "r"(dst), "l"(src), "r"(bytes), "r"(mbar) : "memory");
}
__device__ __forceinline__ void mbar_wait(uint32_t m, uint32_t ph) {
    uint32_t done;
    asm volatile("{\n\t.reg .pred p;\n\t"
                 "mbarrier.try_wait.parity.acquire.cta.shared::cta.b64 p, [%1], %2;\n\t"
                 "selp.b32 %0, 1, 0, p;\n\t}"
                 : "=r"(done) : "r"(m), "r"(ph) : "memory");
    if (!done) {
        asm volatile("{\n\t.reg .pred P1;\n\t"
                     "W_%=:\n\t"
                     "mbarrier.try_wait.parity.acquire.cta.shared::cta.b64 P1, [%0], %1, 0x989680;\n\t"
                     "@P1 bra.uni D_%=;\n\t"
                     "bra.uni W_%=;\n\t"
                     "D_%=:\n\t}"
                     :: "r"(m), "r"(ph) : "memory");
    }
}

__global__ __launch_bounds__(TPB) void pass1(const float* __restrict__ conf) {
    extern __shared__ __align__(16) unsigned char smem[];
    const int b = blockIdx.x;          // 0..36
    const int n = blockIdx.y;          // 0..3
    const int t = threadIdx.x;
    const int warp = t >> 5, lane = t & 31;

    const int rstart = (b * 4800) / CTAS_PER_N;
    const int rend   = ((b + 1) * 4800) / CTAS_PER_N;
    const int nrows  = rend - rstart;     // 129 or 130
    const int nstages = (nrows + RPS - 1) / RPS;
    const size_t grow0 = (size_t)n * LL + rstart;

    float4* tiles = (float4*)(smem + SM_TILES);
    float*  spmax = (float*)(smem + SM_PMAX);
    int*    spcnt = (int*)(smem + SM_PCNT);
    int*    spidx = (int*)(smem + SM_PIDX);
    const uint32_t sbase = smem_u32(smem);
    const uint32_t mbF = sbase + SM_MBAR;            // full[DEPTH]
    const uint32_t mbE = sbase + SM_MBAR + 8*DEPTH;  // empty[DEPTH]

    if (t == 0) {
        for (int s = 0; s < DEPTH; s++) { mbar_init(mbF + 8*s, 1); mbar_init(mbE + 8*s, NW); }
        asm volatile("fence.proxy.async.shared::cta;" ::: "memory");
    }
    __syncthreads();

    if (t >= TPBC) {
        // ---- producer warp (lane 0 of warp 16 does everything) ----
        if (lane == 0) {
            const char* src = (const char*)conf + grow0 * ROWB;
            int buf = 0, ebuf = 0, eph = 0;
            for (int s = 0; s < nstages; s++) {
                if (s >= DEPTH) {
                    mbar_wait(mbE + 8*ebuf, eph);
                    if (++ebuf == DEPTH) { ebuf = 0; eph ^= 1; }
                }
                mbar_expect_tx(mbF + 8*buf, STAGEB);
                bulk_ldg(sbase + buf*STAGEB, src + (size_t)s * STAGEB, STAGEB, mbF + 8*buf);
                if (++buf == DEPTH) buf = 0;
            }
        }
    } else {
        // ---- consumer warps: free-running, no CTA barrier in the loop ----
        const bool tail = t < TAILQ;   // t < 176
        float4 z0 = {0,0,0,0}, z1 = {0,0,0,0}, z2 = {0,0,0,0};

        int buf = 0, ph = 0;
        for (int s = 0; s < nstages; s++) {
            mbar_wait(mbF + 8*buf, ph);

#pragma unroll
            for (int rr = 0; rr < RPS; rr++) {
                const int r = s * RPS + rr;
                if (r >= nrows) break;

                const float4* tp = tiles + (buf * RPS + rr) * NQ + t;
                float4 a0 = tp[0];
                float4 a1 = tp[TPBC];
                float4 a2 = tail ? tp[2*TPBC] : make_float4(0.f,0.f,0.f,0.f);

                z0.x = fmaxf(z0.x, a0.x); z0.y = fmaxf(z0.y, a0.y);
                z0.z = fmaxf(z0.z, a0.z); z0.w = fmaxf(z0.w, a0.w);
                z1.x = fmaxf(z1.x, a1.x); z1.y = fmaxf(z1.y, a1.y);
                z1.z = fmaxf(z1.z, a1.z); z1.w = fmaxf(z1.w, a1.w);
                z2.x = fmaxf(z2.x, a2.x); z2.y = fmaxf(z2.y, a2.y);
                z2.z = fmaxf(z2.z, a2.z); z2.w = fmaxf(z2.w, a2.w);

                float4 rm;
                rm.x = fmaxf(fmaxf(a0.x, a1.x), a2.x);
                rm.y = fmaxf(fmaxf(a0.y, a1.y), a2.y);
                rm.z = fmaxf(fmaxf(a0.z, a1.z), a2.z);
                rm.w = fmaxf(fmaxf(a0.w, a1.w), a2.w);
                float tm = fmaxf(fmaxf(rm.x, rm.y), fmaxf(rm.z, rm.w));

                float wm = __uint_as_float(__reduce_max_sync(0xffffffffu, __float_as_uint(tm)));

                // branch-free tie detection: 12-bit equality mask, monotonic in j
                unsigned mm =
                      (unsigned)(a0.x == wm)        | ((unsigned)(a0.y == wm) << 1)
                    | ((unsigned)(a0.z == wm) << 2) | ((unsigned)(a0.w == wm) << 3)
                    | ((unsigned)(a1.x == wm) << 4) | ((unsigned)(a1.y == wm) << 5)
                    | ((unsigned)(a1.z == wm) << 6) | ((unsigned)(a1.w == wm) << 7)
                    | ((unsigned)(a2.x == wm) << 8) | ((unsigned)(a2.y == wm) << 9)
                    | ((unsigned)(a2.z == wm) <<10) | ((unsigned)(a2.w == wm) <<11);
                unsigned lcnt = (unsigned)__popc(mm);
                unsigned lidx = 0x7fffffffu;
                if (mm) {
                    int bit = __ffs(mm) - 1;
                    lidx = (unsigned)(4*t + ((bit >> 2) << 11) + (bit & 3));  // 2048 = 4*TPBC
                }
                unsigned wcnt = __reduce_add_sync(0xffffffffu, lcnt);
                unsigned widx = __reduce_min_sync(0xffffffffu, lidx);
                if (lane == 0) {
                    spmax[r*NW + warp] = wm;
                    spcnt[r*NW + warp] = (int)wcnt;
                    spidx[r*NW + warp] = (int)widx;
                }
            }

            __syncwarp();
            if (lane == 0) mbar_arrive(mbE + 8*buf);   // this warp done with tiles[buf]
            if (++buf == DEPTH) { buf = 0; ph ^= 1; }
        }

        // flush privatized column-max partials: coalesced float4 stores, no atomics
        float4* cp = (float4*)&g_colpart[((size_t)b * NN + n) * SS] + t;
        cp[0]     = z0;
        cp[TPBC]  = z1;
        if (tail) cp[2*TPBC] = z2;
    }

    __syncthreads();   // spmax/spcnt/spidx complete across all warps

    // combine 16 warp-partials per row
    if (t < nrows) {
        float m = -1.f; int c = 0, ix = 0;
#pragma unroll
        for (int w = 0; w < NW; w++) {
            float om = spmax[t*NW + w];
            if (om > m)       { m = om; c = spcnt[t*NW + w]; ix = spidx[t*NW + w]; }
            else if (om == m) { c += spcnt[t*NW + w]; ix = min(ix, spidx[t*NW + w]); }
        }
        size_t gi = grow0 + t;
        g_rowmax[gi] = m; g_rowj[gi] = ix; g_rowcnt[gi] = c;
    }
}

__device__ __forceinline__ bool valid1(int j) {
    int r = j / W1, c = j % W1;
    return (r >= BR) & (r < H1 - BR) & (c >= BR) & (c < W1 - BR);
}

// warp-collective 37-way colmax fold at column j of batch n
__device__ __forceinline__ float fold_colmax(int n, int j, int lane) {
    float pm = 0.f;
#pragma unroll
    for (int b = lane; b < CTAS_PER_N; b += 32)
        pm = fmaxf(pm, g_colpart[((size_t)b * NN + n) * SS + j]);
    return __uint_as_float(__reduce_max_sync(0xffffffffu, __float_as_uint(pm)));
}

// fused pass2: warp per row; inline colmax fold (no reduce kernel, no g_colmax)
#define P2W 8
__global__ __launch_bounds__(256) void pass2(const float* __restrict__ conf,
                                             float* __restrict__ out) {
    const int warp = threadIdx.x >> 5, lane = threadIdx.x & 31;
    const int gw = blockIdx.x * P2W + warp;        // row id; grid exact: 2400*8 = 19200
    const int n = gw / LL, i = gw % LL;

    const float m  = g_rowmax[gw];
    const int cnt  = g_rowcnt[gw];
    const int jc   = g_rowj[gw];

    const int r0 = i / W0, c0 = i % W0;
    const bool v0 = (r0 >= BR) & (r0 < H0 - BR) & (c0 >= BR) & (c0 < W0 - BR);

    float mconf = 0.f; int jid = 0; float mv = 0.f;
    if (v0 && m > THRV) {
        // jc = global min index of the row max; if it passes the mask it is the
        // first True regardless of ties.
        float cmx = fold_colmax(n, jc, lane);
        if (valid1(jc) && cmx == m) {
            mv = 1.f; jid = jc; mconf = m;
        } else if (cnt > 1) {
            // exact ordered rescan over the (rare) tied row
            const float* rowp = conf + ((size_t)n * LL + i) * SS;
            bool found = false;
            for (int base = 0; base < SS && !found; base += 32) {
                int j = base + lane;
                float v = rowp[j];
                bool ok = (v == m) && valid1(j);
                unsigned bal = __ballot_sync(0xffffffffu, ok);
                while (bal) {
                    int bit = __ffs(bal) - 1; bal &= bal - 1;
                    int jcand = base + bit;
                    float c2 = fold_colmax(n, jcand, lane);
                    if (c2 == m) { jid = jcand; mv = 1.f; mconf = m; found = true; break; }
                }
            }
        }
    }
    if (lane == 0) {
        out[gw]        = mconf;
        out[NL + gw]   = mv;
        out[2*NL + gw] = (float)jid;
    }
}

extern "C" void kernel_launch(void* const* d_in, const int* in_sizes, int n_in,
                              void* d_out, int out_size) {
    const float* conf = (const float*)d_in[0];
    float* out = (float*)d_out;

    cudaFuncSetAttribute(pass1, cudaFuncAttributeMaxDynamicSharedMemorySize, SMEM_REQ);
    dim3 g1(CTAS_PER_N, NN);          // 37 x 4 = 148 CTAs = exactly 1 per SM
    pass1<<<g1, TPB, SMEM_REQ>>>(conf);
    pass2<<<NL / P2W, 256>>>(conf, out);   // 2400 CTAs, warp per row
}

// round 11
// speedup vs baseline: 2.0109x; 2.0109x over previous
#include <cuda_runtime.h>
#include <cstdint>
#include <cstddef>

// Problem constants (fixed by setup_inputs)
#define NN 4
#define H0 60
#define W0 80
#define H1 60
#define W1 80
#define LL (H0*W0)     // 4800 rows
#define SS (H1*W1)     // 4800 cols
#define NL (NN*LL)
#define THRV 0.2f
#define BR 2

#define TPBC 512           // consumer threads
#define TPB  544           // +1 producer warp
#define NW (TPBC/32)       // 16 consumer warps
#define NQ (SS/4)          // 1200 float4 per row
#define ROWB (SS*4)        // 19200 bytes per row
#define RPS 2              // rows per pipeline stage
#define STAGEB (RPS*ROWB)  // 38400
#define DEPTH 5            // pipeline stages (10 rows in flight)
#define CTAS_PER_N 37      // 37*4 = 148 CTAs = 1 per SM
#define MAXROWS 130        // ceil(4800/37)
#define TAILQ (NQ - 2*TPBC) // 176: threads with a 3rd float4

// smem layout (dynamic)
#define SM_TILES 0                          // DEPTH*STAGEB = 192000
#define SM_PMAX  (DEPTH*STAGEB)             // 192000
#define SM_PCNT  (SM_PMAX + MAXROWS*NW*4)   // 200320
#define SM_PIDX  (SM_PCNT + MAXROWS*NW*4)   // 208640
#define SM_MBAR  (SM_PIDX + MAXROWS*NW*4)   // 216960: full[5] then empty[5]
#define SMEM_REQ 217088

// Scratch (no allocations allowed). All of it is plain-stored every run before
// being read -> no init requirements, fully deterministic.
__device__ float    g_colpart[(size_t)CTAS_PER_N*NN*SS];  // per-CTA colmax partials, 2.84 MB
__device__ float    g_colmax[NN*SS];     // folded column maxes
__device__ float    g_rowmax[NL];
__device__ int      g_rowj[NL];          // min index achieving rowmax
__device__ int      g_rowcnt[NL];        // count of elements == rowmax

__device__ __forceinline__ uint32_t smem_u32(const void* p) {
    uint32_t a;
    asm("{ .reg .u64 t; cvta.to.shared.u64 t, %1; cvt.u32.u64 %0, t; }" : "=r"(a) : "l"(p));
    return a;
}
__device__ __forceinline__ void mbar_init(uint32_t m, uint32_t cnt) {
    asm volatile("mbarrier.init.shared.b64 [%0], %1;" :: "r"(m), "r"(cnt) : "memory");
}
__device__ __forceinline__ void mbar_expect_tx(uint32_t m, uint32_t bytes) {
    asm volatile("mbarrier.arrive.expect_tx.shared.b64 _, [%0], %1;" :: "r"(m), "r"(bytes) : "memory");
}
__device__ __forceinline__ void mbar_arrive(uint32_t m) {
    asm volatile("mbarrier.arrive.shared.b64 _, [%0];" :: "r"(m) : "memory");
}
__device__ __forceinline__ void bulk_ldg(uint32_t dst, const void* src, uint32_t bytes, uint32_t mbar) {
    asm volatile("cp.async.bulk.shared::cluster.global.mbarrier::complete_tx::bytes [%0], [%1], %2, [%3];"
                 :: "r"(dst), "l"(src), "r"(bytes), "r"(mbar) : "memory");
}
__device__ __forceinline__ void mbar_wait(uint32_t m, uint32_t ph) {
    uint32_t done;
    asm volatile("{\n\t.reg .pred p;\n\t"
                 "mbarrier.try_wait.parity.acquire.cta.shared::cta.b64 p, [%1], %2;\n\t"
                 "selp.b32 %0, 1, 0, p;\n\t}"
                 : "=r"(done) : "r"(m), "r"(ph) : "memory");
    if (!done) {
        asm volatile("{\n\t.reg .pred P1;\n\t"
                     "W_%=:\n\t"
                     "mbarrier.try_wait.parity.acquire.cta.shared::cta.b64 P1, [%0], %1, 0x989680;\n\t"
                     "@P1 bra.uni D_%=;\n\t"
                     "bra.uni W_%=;\n\t"
                     "D_%=:\n\t}"
                     :: "r"(m), "r"(ph) : "memory");
    }
}

__global__ __launch_bounds__(TPB) void pass1(const float* __restrict__ conf) {
    extern __shared__ __align__(16) unsigned char smem[];
    const int b = blockIdx.x;          // 0..36
    const int n = blockIdx.y;          // 0..3
    const int t = threadIdx.x;
    const int warp = t >> 5, lane = t & 31;

    const int rstart = (b * 4800) / CTAS_PER_N;
    const int rend   = ((b + 1) * 4800) / CTAS_PER_N;
    const int nrows  = rend - rstart;     // 129 or 130
    const int nstages = (nrows + RPS - 1) / RPS;
    const size_t grow0 = (size_t)n * LL + rstart;

    float4* tiles = (float4*)(smem + SM_TILES);
    float*  spmax = (float*)(smem + SM_PMAX);
    int*    spcnt = (int*)(smem + SM_PCNT);
    int*    spidx = (int*)(smem + SM_PIDX);
    const uint32_t sbase = smem_u32(smem);
    const uint32_t mbF = sbase + SM_MBAR;            // full[DEPTH]
    const uint32_t mbE = sbase + SM_MBAR + 8*DEPTH;  // empty[DEPTH]

    if (t == 0) {
        for (int s = 0; s < DEPTH; s++) { mbar_init(mbF + 8*s, 1); mbar_init(mbE + 8*s, NW); }
        asm volatile("fence.proxy.async.shared::cta;" ::: "memory");
    }
    __syncthreads();

    if (t >= TPBC) {
        // ---- producer warp (lane 0 of warp 16 does everything) ----
        if (lane == 0) {
            const char* src = (const char*)conf + grow0 * ROWB;
            int buf = 0, ebuf = 0, eph = 0;
            for (int s = 0; s < nstages; s++) {
                if (s >= DEPTH) {
                    mbar_wait(mbE + 8*ebuf, eph);
                    if (++ebuf == DEPTH) { ebuf = 0; eph ^= 1; }
                }
                mbar_expect_tx(mbF + 8*buf, STAGEB);
                bulk_ldg(sbase + buf*STAGEB, src + (size_t)s * STAGEB, STAGEB, mbF + 8*buf);
                if (++buf == DEPTH) buf = 0;
            }
        }
    } else {
        // ---- consumer warps: free-running, no CTA barrier in the loop ----
        const bool tail = t < TAILQ;   // t < 176
        float4 z0 = {0,0,0,0}, z1 = {0,0,0,0}, z2 = {0,0,0,0};

        int buf = 0, ph = 0;
        for (int s = 0; s < nstages; s++) {
            mbar_wait(mbF + 8*buf, ph);

#pragma unroll
            for (int rr = 0; rr < RPS; rr++) {
                const int r = s * RPS + rr;
                if (r >= nrows) break;

                const float4* tp = tiles + (buf * RPS + rr) * NQ + t;
                float4 a0 = tp[0];
                float4 a1 = tp[TPBC];
                float4 a2 = tail ? tp[2*TPBC] : make_float4(0.f,0.f,0.f,0.f);

                z0.x = fmaxf(z0.x, a0.x); z0.y = fmaxf(z0.y, a0.y);
                z0.z = fmaxf(z0.z, a0.z); z0.w = fmaxf(z0.w, a0.w);
                z1.x = fmaxf(z1.x, a1.x); z1.y = fmaxf(z1.y, a1.y);
                z1.z = fmaxf(z1.z, a1.z); z1.w = fmaxf(z1.w, a1.w);
                z2.x = fmaxf(z2.x, a2.x); z2.y = fmaxf(z2.y, a2.y);
                z2.z = fmaxf(z2.z, a2.z); z2.w = fmaxf(z2.w, a2.w);

                float4 rm;
                rm.x = fmaxf(fmaxf(a0.x, a1.x), a2.x);
                rm.y = fmaxf(fmaxf(a0.y, a1.y), a2.y);
                rm.z = fmaxf(fmaxf(a0.z, a1.z), a2.z);
                rm.w = fmaxf(fmaxf(a0.w, a1.w), a2.w);
                float tm = fmaxf(fmaxf(rm.x, rm.y), fmaxf(rm.z, rm.w));

                float wm = __uint_as_float(__reduce_max_sync(0xffffffffu, __float_as_uint(tm)));

                // branch-free tie detection: 12-bit equality mask, monotonic in j
                unsigned mm =
                      (unsigned)(a0.x == wm)        | ((unsigned)(a0.y == wm) << 1)
                    | ((unsigned)(a0.z == wm) << 2) | ((unsigned)(a0.w == wm) << 3)
                    | ((unsigned)(a1.x == wm) << 4) | ((unsigned)(a1.y == wm) << 5)
                    | ((unsigned)(a1.z == wm) << 6) | ((unsigned)(a1.w == wm) << 7)
                    | ((unsigned)(a2.x == wm) << 8) | ((unsigned)(a2.y == wm) << 9)
                    | ((unsigned)(a2.z == wm) <<10) | ((unsigned)(a2.w == wm) <<11);
                unsigned lcnt = (unsigned)__popc(mm);
                unsigned lidx = 0x7fffffffu;
                if (mm) {
                    int bit = __ffs(mm) - 1;
                    lidx = (unsigned)(4*t + ((bit >> 2) << 11) + (bit & 3));  // 2048 = 4*TPBC
                }
                unsigned wcnt = __reduce_add_sync(0xffffffffu, lcnt);
                unsigned widx = __reduce_min_sync(0xffffffffu, lidx);
                if (lane == 0) {
                    spmax[r*NW + warp] = wm;
                    spcnt[r*NW + warp] = (int)wcnt;
                    spidx[r*NW + warp] = (int)widx;
                }
            }

            __syncwarp();
            if (lane == 0) mbar_arrive(mbE + 8*buf);   // this warp done with tiles[buf]
            if (++buf == DEPTH) { buf = 0; ph ^= 1; }
        }

        // flush privatized column-max partials: coalesced float4 stores, no atomics
        float4* cp = (float4*)&g_colpart[((size_t)b * NN + n) * SS] + t;
        cp[0]     = z0;
        cp[TPBC]  = z1;
        if (tail) cp[2*TPBC] = z2;
    }

    __syncthreads();   // spmax/spcnt/spidx complete across all warps

    // combine 16 warp-partials per row
    if (t < nrows) {
        float m = -1.f; int c = 0, ix = 0;
#pragma unroll
        for (int w = 0; w < NW; w++) {
            float om = spmax[t*NW + w];
            if (om > m)       { m = om; c = spcnt[t*NW + w]; ix = spidx[t*NW + w]; }
            else if (om == m) { c += spcnt[t*NW + w]; ix = min(ix, spidx[t*NW + w]); }
        }
        size_t gi = grow0 + t;
        g_rowmax[gi] = m; g_rowj[gi] = ix; g_rowcnt[gi] = c;
    }
}

// fold 37 per-CTA partials per column -> g_colmax. One thread per (n, j) scalar:
// NN*SS = 19200 threads; per b-slice consecutive threads read consecutive floats
// (coalesced), 37 independent loads per thread (full MLP), 2.84 MB L2-resident.
__global__ __launch_bounds__(256) void reduce_colmax() {
    int idx = blockIdx.x * blockDim.x + threadIdx.x;    // 0 .. NN*SS-1
    int n = idx / SS, j = idx % SS;
    float m = 0.f;
#pragma unroll
    for (int b = 0; b < CTAS_PER_N; b++)
        m = fmaxf(m, g_colpart[((size_t)b * NN + n) * SS + j]);
    g_colmax[idx] = m;
}

__device__ __forceinline__ bool valid1(int j) {
    int r = j / W1, c = j % W1;
    return (r >= BR) & (r < H1 - BR) & (c >= BR) & (c < W1 - BR);
}

// thread-per-row fast path + CTA-cooperative rescan for the rare ambiguous rows
#define P2B 256
__global__ __launch_bounds__(P2B) void pass2(const float* __restrict__ conf,
                                             float* __restrict__ out) {
    __shared__ int   s_list[P2B];
    __shared__ float s_m[P2B];
    __shared__ int s_nl;
    __shared__ unsigned s_best;
    const int tid = threadIdx.x;
    const int gw  = blockIdx.x * P2B + tid;        // row id; grid exact: 75*256=19200
    if (tid == 0) s_nl = 0;
    __syncthreads();

    const int n = gw / LL, i = gw % LL;
    const float m  = g_rowmax[gw];
    const int cnt  = g_rowcnt[gw];
    const int jc   = g_rowj[gw];

    const int r0 = i / W0, c0 = i % W0;
    const bool v0 = (r0 >= BR) & (r0 < H0 - BR) & (c0 >= BR) & (c0 < W0 - BR);

    float mconf = 0.f; int jid = 0; float mv = 0.f;
    bool need = false;
    if (v0 && m > THRV) {
        // jc is the global min-index of the row max; if it passes the mask it is
        // the first True regardless of ties.
        if (valid1(jc) && g_colmax[n * SS + jc] == m) {
            mv = 1.f; jid = jc; mconf = m;
        } else if (cnt > 1) {
            need = true;            // a later tied position may pass -> exact rescan
        }
    }
    if (need) { int p = atomicAdd(&s_nl, 1); s_list[p] = tid; s_m[tid] = m; }
    __syncthreads();
    if (!need) {
        out[gw]        = mconf;
        out[NL + gw]   = mv;
        out[2*NL + gw] = (float)jid;
    }

    const int nl = s_nl;
    for (int w = 0; w < nl; w++) {
        const int lrow = s_list[w];
        const int grow = blockIdx.x * P2B + lrow;
        const int nn = grow / LL, ii = grow % LL;
        const float mm = s_m[lrow];
        const float* rowp = conf + ((size_t)nn * LL + ii) * SS;
        if (tid == 0) s_best = 0x7fffffffu;
        __syncthreads();
        unsigned lb = 0x7fffffffu;
        for (int j = tid; j < SS; j += P2B) {
            float v = rowp[j];
            if (v == mm && valid1(j) && g_colmax[nn * SS + j] == v)
                lb = min(lb, (unsigned)j);
        }
        if (lb != 0x7fffffffu) atomicMin(&s_best, lb);
        __syncthreads();
        if (tid == 0) {
            unsigned bsel = s_best;
            bool hit = (bsel != 0x7fffffffu);
            out[grow]        = hit ? mm : 0.f;
            out[NL + grow]   = hit ? 1.f : 0.f;
            out[2*NL + grow] = hit ? (float)bsel : 0.f;
        }
        __syncthreads();
    }
}

extern "C" void kernel_launch(void* const* d_in, const int* in_sizes, int n_in,
                              void* d_out, int out_size) {
    const float* conf = (const float*)d_in[0];
    float* out = (float*)d_out;

    cudaFuncSetAttribute(pass1, cudaFuncAttributeMaxDynamicSharedMemorySize, SMEM_REQ);
    dim3 g1(CTAS_PER_N, NN);          // 37 x 4 = 148 CTAs = exactly 1 per SM
    pass1<<<g1, TPB, SMEM_REQ>>>(conf);
    reduce_colmax<<<NN*SS/256, 256>>>();           // 75 CTAs, coalesced 37-way fold
    pass2<<<NL / P2B, P2B>>>(conf, out);           // 75 CTAs
}

// round 12
// speedup vs baseline: 2.0257x; 1.0074x over previous
#include <cuda_runtime.h>
#include <cstdint>
#include <cstddef>

// Problem constants (fixed by setup_inputs)
#define NN 4
#define H0 60
#define W0 80
#define H1 60
#define W1 80
#define LL (H0*W0)     // 4800 rows
#define SS (H1*W1)     // 4800 cols
#define NL (NN*LL)
#define THRV 0.2f
#define BR 2

#define TPB 512
#define NW (TPB/32)        // 16 warps
#define NQ (SS/4)          // 1200 float4 per row
#define ROWB (SS*4)        // 19200 bytes per row
#define RPS 2              // rows per pipeline stage
#define STAGEB (RPS*ROWB)  // 38400
#define DEPTH 5            // pipeline stages (10 rows in flight)
#define CTAS_PER_N 37      // 37*4 = 148 CTAs = 1 per SM
#define MAXROWS 130        // ceil(4800/37)
#define TAILQ (NQ - 2*TPB) // 176: threads with a 3rd float4

// smem layout (dynamic)
#define SM_TILES 0                          // DEPTH*STAGEB = 192000
#define SM_PMAX  (DEPTH*STAGEB)             // 192000
#define SM_PCNT  (SM_PMAX + MAXROWS*NW*4)   // 200320
#define SM_PIDX  (SM_PCNT + MAXROWS*NW*4)   // 208640
#define SM_MBAR  (SM_PIDX + MAXROWS*NW*4)   // 216960
#define SMEM_REQ 217088

// Scratch (no allocations allowed). All data is plain-stored before being read
// each run; g_bar is reset by pass1 each run -> deterministic across replays.
__device__ float    g_colpart[(size_t)CTAS_PER_N*NN*SS];  // per-CTA colmax partials, 2.84 MB
__device__ float    g_colmax[NN*SS];     // folded column maxes
__device__ float    g_rowmax[NL];
__device__ int      g_rowj[NL];          // min index achieving rowmax
__device__ int      g_rowcnt[NL];        // count of elements == rowmax
__device__ int      g_bar;               // software grid barrier for pass2

__device__ __forceinline__ uint32_t smem_u32(const void* p) {
    uint32_t a;
    asm("{ .reg .u64 t; cvta.to.shared.u64 t, %1; cvt.u32.u64 %0, t; }" : "=r"(a) : "l"(p));
    return a;
}
__device__ __forceinline__ void mbar_init(uint32_t m, uint32_t cnt) {
    asm volatile("mbarrier.init.shared.b64 [%0], %1;" :: "r"(m), "r"(cnt) : "memory");
}
__device__ __forceinline__ void mbar_expect_tx(uint32_t m, uint32_t bytes) {
    asm volatile("mbarrier.arrive.expect_tx.shared.b64 _, [%0], %1;" :: "r"(m), "r"(bytes) : "memory");
}
__device__ __forceinline__ void bulk_ldg(uint32_t dst, const void* src, uint32_t bytes, uint32_t mbar) {
    asm volatile("cp.async.bulk.shared::cluster.global.mbarrier::complete_tx::bytes [%0], [%1], %2, [%3];"
                 :: "r"(dst), "l"(src), "r"(bytes), "r"(mbar) : "memory");
}
__device__ __forceinline__ void mbar_wait(uint32_t m, uint32_t ph) {
    uint32_t done;
    asm volatile("{\n\t.reg .pred p;\n\t"
                 "mbarrier.try_wait.parity.acquire.cta.shared::cta.b64 p, [%1], %2;\n\t"
                 "selp.b32 %0, 1, 0, p;\n\t}"
                 : "=r"(done) : "r"(m), "r"(ph) : "memory");
    if (!done) {
        asm volatile("{\n\t.reg .pred P1;\n\t"
                     "W_%=:\n\t"
                     "mbarrier.try_wait.parity.acquire.cta.shared::cta.b64 P1, [%0], %1, 0x989680;\n\t"
                     "@P1 bra.uni D_%=;\n\t"
                     "bra.uni W_%=;\n\t"
                     "D_%=:\n\t}"
                     :: "r"(m), "r"(ph) : "memory");
    }
}

__global__ __launch_bounds__(TPB) void pass1(const float* __restrict__ conf) {
    extern __shared__ __align__(16) unsigned char smem[];
    const int b = blockIdx.x;          // 0..36
    const int n = blockIdx.y;          // 0..3
    const int t = threadIdx.x;
    const int warp = t >> 5, lane = t & 31;
    const bool tail = t < TAILQ;       // t < 176

    if (b == 0 && n == 0 && t == 0) g_bar = 0;   // reset pass2's grid barrier

    const int rstart = (b * 4800) / CTAS_PER_N;
    const int rend   = ((b + 1) * 4800) / CTAS_PER_N;
    const int nrows  = rend - rstart;     // 129 or 130
    const int nstages = (nrows + RPS - 1) / RPS;
    const size_t grow0 = (size_t)n * LL + rstart;

    float4* tiles = (float4*)(smem + SM_TILES);
    float*  spmax = (float*)(smem + SM_PMAX);
    int*    spcnt = (int*)(smem + SM_PCNT);
    int*    spidx = (int*)(smem + SM_PIDX);
    const uint32_t sbase = smem_u32(smem);
    const uint32_t mb0   = sbase + SM_MBAR;

    // init pipeline
    if (t == 0) {
        for (int s = 0; s < DEPTH; s++) mbar_init(mb0 + 8*s, 1);
        asm volatile("fence.proxy.async.shared::cta;" ::: "memory");
    }
    __syncthreads();
    if (t == 0) {
        // stage s covers rows [s*RPS, s*RPS+1]; always load full 2 rows (an odd-nrows
        // CTA reads 1 unused in-bounds row; the global-last CTA has even nrows).
        for (int s = 0; s < DEPTH; s++) {
            mbar_expect_tx(mb0 + 8*s, STAGEB);
            bulk_ldg(sbase + s*STAGEB, (const char*)conf + (grow0 + s*RPS) * ROWB, STAGEB, mb0 + 8*s);
        }
    }

    // colmax accumulators (fma pipe; values are nonneg)
    float4 z0 = {0,0,0,0}, z1 = {0,0,0,0}, z2 = {0,0,0,0};

    int stage = 0, ph = 0;
    for (int s = 0; s < nstages; s++) {
        mbar_wait(mb0 + 8*stage, ph);

#pragma unroll
        for (int rr = 0; rr < RPS; rr++) {
            const int r = s * RPS + rr;
            if (r >= nrows) break;

            const float4* tp = tiles + (stage * RPS + rr) * NQ + t;
            float4 a0 = tp[0];
            float4 a1 = tp[TPB];
            float4 a2 = tail ? tp[2*TPB] : make_float4(0.f,0.f,0.f,0.f);

            z0.x = fmaxf(z0.x, a0.x); z0.y = fmaxf(z0.y, a0.y);
            z0.z = fmaxf(z0.z, a0.z); z0.w = fmaxf(z0.w, a0.w);
            z1.x = fmaxf(z1.x, a1.x); z1.y = fmaxf(z1.y, a1.y);
            z1.z = fmaxf(z1.z, a1.z); z1.w = fmaxf(z1.w, a1.w);
            z2.x = fmaxf(z2.x, a2.x); z2.y = fmaxf(z2.y, a2.y);
            z2.z = fmaxf(z2.z, a2.z); z2.w = fmaxf(z2.w, a2.w);

            float4 rm;
            rm.x = fmaxf(fmaxf(a0.x, a1.x), a2.x);
            rm.y = fmaxf(fmaxf(a0.y, a1.y), a2.y);
            rm.z = fmaxf(fmaxf(a0.z, a1.z), a2.z);
            rm.w = fmaxf(fmaxf(a0.w, a1.w), a2.w);
            float tm = fmaxf(fmaxf(rm.x, rm.y), fmaxf(rm.z, rm.w));

            float wm = __uint_as_float(__reduce_max_sync(0xffffffffu, __float_as_uint(tm)));

            // branch-free tie detection: 12-bit equality mask, monotonic in j
            unsigned mm =
                  (unsigned)(a0.x == wm)        | ((unsigned)(a0.y == wm) << 1)
                | ((unsigned)(a0.z == wm) << 2) | ((unsigned)(a0.w == wm) << 3)
                | ((unsigned)(a1.x == wm) << 4) | ((unsigned)(a1.y == wm) << 5)
                | ((unsigned)(a1.z == wm) << 6) | ((unsigned)(a1.w == wm) << 7)
                | ((unsigned)(a2.x == wm) << 8) | ((unsigned)(a2.y == wm) << 9)
                | ((unsigned)(a2.z == wm) <<10) | ((unsigned)(a2.w == wm) <<11);
            unsigned lcnt = (unsigned)__popc(mm);
            unsigned lidx = 0x7fffffffu;
            if (mm) {
                int bit = __ffs(mm) - 1;
                lidx = (unsigned)(4*t + ((bit >> 2) << 11) + (bit & 3));  // 2048 = 4*TPB
            }
            unsigned wcnt = __reduce_add_sync(0xffffffffu, lcnt);
            unsigned widx = __reduce_min_sync(0xffffffffu, lidx);
            if (lane == 0) {
                spmax[r*NW + warp] = wm;
                spcnt[r*NW + warp] = (int)wcnt;
                spidx[r*NW + warp] = (int)widx;
            }
        }

        __syncthreads();                 // everyone done reading tiles[stage]
        int sn = s + DEPTH;
        if (t == 0 && sn * RPS < nrows) {
            mbar_expect_tx(mb0 + 8*stage, STAGEB);
            bulk_ldg(sbase + stage*STAGEB, (const char*)conf + (grow0 + sn*RPS) * ROWB, STAGEB, mb0 + 8*stage);
        }
        if (++stage == DEPTH) { stage = 0; ph ^= 1; }
    }
    __syncthreads();

    // combine 16 warp-partials per row
    if (t < nrows) {
        float m = -1.f; int c = 0, ix = 0;
#pragma unroll
        for (int w = 0; w < NW; w++) {
            float om = spmax[t*NW + w];
            if (om > m)       { m = om; c = spcnt[t*NW + w]; ix = spidx[t*NW + w]; }
            else if (om == m) { c += spcnt[t*NW + w]; ix = min(ix, spidx[t*NW + w]); }
        }
        size_t gi = grow0 + t;
        g_rowmax[gi] = m; g_rowj[gi] = ix; g_rowcnt[gi] = c;
    }

    // flush privatized column-max partials: coalesced float4 stores, no atomics
    {
        float4* cp = (float4*)&g_colpart[((size_t)b * NN + n) * SS] + t;
        cp[0]     = z0;
        cp[TPB]   = z1;
        if (tail) cp[2*TPB] = z2;
    }
}

__device__ __forceinline__ bool valid1(int j) {
    int r = j / W1, c = j % W1;
    return (r >= BR) & (r < H1 - BR) & (c >= BR) & (c < W1 - BR);
}

// Fused: colmax fold + grid barrier + matching. grid = 148 CTAs (all resident
// -> spin barrier is deadlock-free), 256 threads.
#define P2G 148
#define P2ROWS 130          // ceil(19200/148)
#define P2B 256
__global__ __launch_bounds__(P2B) void pass2(const float* __restrict__ conf,
                                             float* __restrict__ out) {
    __shared__ int   s_list[P2ROWS];
    __shared__ float s_m[P2ROWS];
    __shared__ int s_nl;
    __shared__ unsigned s_best;
    const int tid  = threadIdx.x;
    const int base = blockIdx.x * P2ROWS;

    // Phase A: fold 37 partials for this CTA's slice of columns (coalesced)
    if (tid < P2ROWS) {
        int idx = base + tid;
        if (idx < NN*SS) {
            int n = idx / SS, j = idx % SS;
            float m = 0.f;
#pragma unroll
            for (int b2 = 0; b2 < CTAS_PER_N; b2++)
                m = fmaxf(m, g_colpart[((size_t)b2 * NN + n) * SS + j]);
            g_colmax[idx] = m;
        }
    }
    __threadfence();        // make this CTA's g_colmax stores visible
    __syncthreads();

    // Phase B: software grid barrier (all P2G CTAs resident)
    if (tid == 0) {
        atomicAdd(&g_bar, 1);
        while (*(volatile int*)&g_bar < P2G) __nanosleep(64);
        s_nl = 0;
    }
    __syncthreads();

    // Phase C: thread-per-row matching
    const int gw = base + tid;                   // row id
    const bool rowok = (tid < P2ROWS) && (gw < NL);

    float mconf = 0.f; int jid = 0; float mv = 0.f;
    bool need = false;
    float m = 0.f;
    if (rowok) {
        const int n = gw / LL, i = gw % LL;
        m = g_rowmax[gw];
        const int cnt = g_rowcnt[gw];
        const int jc  = g_rowj[gw];

        const int r0 = i / W0, c0 = i % W0;
        const bool v0 = (r0 >= BR) & (r0 < H0 - BR) & (c0 >= BR) & (c0 < W0 - BR);

        if (v0 && m > THRV) {
            // jc is the global min-index of the row max; if it passes the mask
            // it is the first True regardless of ties.
            if (valid1(jc) && g_colmax[n * SS + jc] == m) {
                mv = 1.f; jid = jc; mconf = m;
            } else if (cnt > 1) {
                need = true;        // a later tied position may pass -> exact rescan
            }
        }
    }
    if (need) { int p = atomicAdd(&s_nl, 1); s_list[p] = tid; s_m[tid] = m; }
    __syncthreads();
    if (rowok && !need) {
        out[gw]        = mconf;
        out[NL + gw]   = mv;
        out[2*NL + gw] = (float)jid;
    }

    const int nl = s_nl;
    for (int w = 0; w < nl; w++) {
        const int lrow = s_list[w];
        const int grow = base + lrow;
        const int nn = grow / LL, ii = grow % LL;
        const float mm = s_m[lrow];
        const float* rowp = conf + ((size_t)nn * LL + ii) * SS;
        if (tid == 0) s_best = 0x7fffffffu;
        __syncthreads();
        unsigned lb = 0x7fffffffu;
        for (int j = tid; j < SS; j += P2B) {
            float v = rowp[j];
            if (v == mm && valid1(j) && g_colmax[nn * SS + j] == v)
                lb = min(lb, (unsigned)j);
        }
        if (lb != 0x7fffffffu) atomicMin(&s_best, lb);
        __syncthreads();
        if (tid == 0) {
            unsigned bsel = s_best;
            bool hit = (bsel != 0x7fffffffu);
            out[grow]        = hit ? mm : 0.f;
            out[NL + grow]   = hit ? 1.f : 0.f;
            out[2*NL + grow] = hit ? (float)bsel : 0.f;
        }
        __syncthreads();
    }
}

extern "C" void kernel_launch(void* const* d_in, const int* in_sizes, int n_in,
                              void* d_out, int out_size) {
    const float* conf = (const float*)d_in[0];
    float* out = (float*)d_out;

    cudaFuncSetAttribute(pass1, cudaFuncAttributeMaxDynamicSharedMemorySize, SMEM_REQ);
    dim3 g1(CTAS_PER_N, NN);          // 37 x 4 = 148 CTAs = exactly 1 per SM
    pass1<<<g1, TPB, SMEM_REQ>>>(conf);
    pass2<<<P2G, P2B>>>(conf, out);   // fused fold + barrier + match
}

// round 13
// speedup vs baseline: 2.0646x; 1.0192x over previous
#include <cuda_runtime.h>
#include <cstdint>
#include <cstddef>

// Problem constants (fixed by setup_inputs)
#define NN 4
#define H0 60
#define W0 80
#define H1 60
#define W1 80
#define LL (H0*W0)     // 4800 rows
#define SS (H1*W1)     // 4800 cols
#define NL (NN*LL)
#define THRV 0.2f
#define BR 2

#define TPB 512
#define NW (TPB/32)        // 16 warps
#define NQ (SS/4)          // 1200 float4 per row
#define ROWB (SS*4)        // 19200 bytes per row
#define RPS 2              // rows per pipeline stage
#define STAGEB (RPS*ROWB)  // 38400
#define DEPTH 5            // pipeline stages (10 rows in flight)
#define CTAS_PER_N 37      // 37*4 = 148 CTAs = 1 per SM (all co-resident)
#define NCTA 148
#define MAXROWS 130        // ceil(4800/37)
#define TAILQ (NQ - 2*TPB) // 176: threads with a 3rd float4
#define COLS_PER_CTA 130   // ceil(19200/148)
#define RESCAN_K 10        // ceil(4800/512)

// smem layout (dynamic)
#define SM_TILES 0                          // DEPTH*STAGEB = 192000
#define SM_PMAX  (DEPTH*STAGEB)             // 192000
#define SM_PCNT  (SM_PMAX + MAXROWS*NW*4)   // 200320
#define SM_PIDX  (SM_PCNT + MAXROWS*NW*4)   // 208640
#define SM_MBAR  (SM_PIDX + MAXROWS*NW*4)   // 216960
#define SMEM_REQ 217088

// Scratch (no allocations allowed). colpart/colmax are plain-stored before
// being read each run. g_bar is a MONOTONIC ticket counter (never reset) ->
// identical work every launch, safe across graph replays.
__device__ float    g_colpart[(size_t)CTAS_PER_N*NN*SS];  // per-CTA colmax partials, 2.84 MB
__device__ float    g_colmax[NN*SS];     // folded column maxes
__device__ int      g_bar;               // monotonic grid-barrier ticket counter

__device__ __forceinline__ uint32_t smem_u32(const void* p) {
    uint32_t a;
    asm("{ .reg .u64 t; cvta.to.shared.u64 t, %1; cvt.u32.u64 %0, t; }" : "=r"(a) : "l"(p));
    return a;
}
__device__ __forceinline__ void mbar_init(uint32_t m, uint32_t cnt) {
    asm volatile("mbarrier.init.shared.b64 [%0], %1;" :: "r"(m), "r"(cnt) : "memory");
}
__device__ __forceinline__ void mbar_expect_tx(uint32_t m, uint32_t bytes) {
    asm volatile("mbarrier.arrive.expect_tx.shared.b64 _, [%0], %1;" :: "r"(m), "r"(bytes) : "memory");
}
__device__ __forceinline__ void bulk_ldg(uint32_t dst, const void* src, uint32_t bytes, uint32_t mbar) {
    asm volatile("cp.async.bulk.shared::cluster.global.mbarrier::complete_tx::bytes [%0], [%1], %2, [%3];"
                 :: "r"(dst), "l"(src), "r"(bytes), "r"(mbar) : "memory");
}
__device__ __forceinline__ void mbar_wait(uint32_t m, uint32_t ph) {
    uint32_t done;
    asm volatile("{\n\t.reg .pred p;\n\t"
                 "mbarrier.try_wait.parity.acquire.cta.shared::cta.b64 p, [%1], %2;\n\t"
                 "selp.b32 %0, 1, 0, p;\n\t}"
                 : "=r"(done) : "r"(m), "r"(ph) : "memory");
    if (!done) {
        asm volatile("{\n\t.reg .pred P1;\n\t"
                     "W_%=:\n\t"
                     "mbarrier.try_wait.parity.acquire.cta.shared::cta.b64 P1, [%0], %1, 0x989680;\n\t"
                     "@P1 bra.uni D_%=;\n\t"
                     "bra.uni W_%=;\n\t"
                     "D_%=:\n\t}"
                     :: "r"(m), "r"(ph) : "memory");
    }
}

// Monotonic grid barrier: all NCTA CTAs co-resident (grid=148, 1/SM).
// ticket/NCTA identifies the barrier instance; no reset needed, ever.
__device__ __forceinline__ void grid_bar() {
    __syncthreads();
    if (threadIdx.x == 0) {
        __threadfence();
        int ticket = atomicAdd(&g_bar, 1);
        int target = (ticket / NCTA + 1) * NCTA;
        while (*(volatile int*)&g_bar < target) __nanosleep(64);
        __threadfence();
    }
    __syncthreads();
}

__device__ __forceinline__ bool valid1(int j) {
    int r = j / W1, c = j % W1;
    return (r >= BR) & (r < H1 - BR) & (c >= BR) & (c < W1 - BR);
}

__global__ __launch_bounds__(TPB) void fused(const float* __restrict__ conf,
                                             float* __restrict__ out) {
    extern __shared__ __align__(16) unsigned char smem[];
    __shared__ int   s_list[MAXROWS];
    __shared__ float s_m[MAXROWS];
    __shared__ int s_nl;
    __shared__ unsigned s_best;

    const int b = blockIdx.x;          // 0..36
    const int n = blockIdx.y;          // 0..3
    const int t = threadIdx.x;
    const int warp = t >> 5, lane = t & 31;
    const bool tail = t < TAILQ;       // t < 176

    const int rstart = (b * 4800) / CTAS_PER_N;
    const int rend   = ((b + 1) * 4800) / CTAS_PER_N;
    const int nrows  = rend - rstart;     // 129 or 130
    const int nstages = (nrows + RPS - 1) / RPS;
    const size_t grow0 = (size_t)n * LL + rstart;

    float4* tiles = (float4*)(smem + SM_TILES);
    float*  spmax = (float*)(smem + SM_PMAX);
    int*    spcnt = (int*)(smem + SM_PCNT);
    int*    spidx = (int*)(smem + SM_PIDX);
    const uint32_t sbase = smem_u32(smem);
    const uint32_t mb0   = sbase + SM_MBAR;

    // ---------------- Phase 1: stream + reduce (R8-proven pipeline) ----------
    if (t == 0) {
        for (int s = 0; s < DEPTH; s++) mbar_init(mb0 + 8*s, 1);
        asm volatile("fence.proxy.async.shared::cta;" ::: "memory");
    }
    __syncthreads();
    if (t == 0) {
        // stage s covers rows [s*RPS, s*RPS+1]; always load 2 full rows (odd-nrows
        // CTAs read 1 unused in-bounds row; the global-last CTA has even nrows).
        for (int s = 0; s < DEPTH; s++) {
            mbar_expect_tx(mb0 + 8*s, STAGEB);
            bulk_ldg(sbase + s*STAGEB, (const char*)conf + (grow0 + s*RPS) * ROWB, STAGEB, mb0 + 8*s);
        }
    }

    float4 z0 = {0,0,0,0}, z1 = {0,0,0,0}, z2 = {0,0,0,0};   // colmax accumulators

    int stage = 0, ph = 0;
    for (int s = 0; s < nstages; s++) {
        mbar_wait(mb0 + 8*stage, ph);

#pragma unroll
        for (int rr = 0; rr < RPS; rr++) {
            const int r = s * RPS + rr;
            if (r >= nrows) break;

            const float4* tp = tiles + (stage * RPS + rr) * NQ + t;
            float4 a0 = tp[0];
            float4 a1 = tp[TPB];
            float4 a2 = tail ? tp[2*TPB] : make_float4(0.f,0.f,0.f,0.f);

            z0.x = fmaxf(z0.x, a0.x); z0.y = fmaxf(z0.y, a0.y);
            z0.z = fmaxf(z0.z, a0.z); z0.w = fmaxf(z0.w, a0.w);
            z1.x = fmaxf(z1.x, a1.x); z1.y = fmaxf(z1.y, a1.y);
            z1.z = fmaxf(z1.z, a1.z); z1.w = fmaxf(z1.w, a1.w);
            z2.x = fmaxf(z2.x, a2.x); z2.y = fmaxf(z2.y, a2.y);
            z2.z = fmaxf(z2.z, a2.z); z2.w = fmaxf(z2.w, a2.w);

            float4 rm;
            rm.x = fmaxf(fmaxf(a0.x, a1.x), a2.x);
            rm.y = fmaxf(fmaxf(a0.y, a1.y), a2.y);
            rm.z = fmaxf(fmaxf(a0.z, a1.z), a2.z);
            rm.w = fmaxf(fmaxf(a0.w, a1.w), a2.w);
            float tm = fmaxf(fmaxf(rm.x, rm.y), fmaxf(rm.z, rm.w));

            float wm = __uint_as_float(__reduce_max_sync(0xffffffffu, __float_as_uint(tm)));

            // branch-free tie detection: 12-bit equality mask, monotonic in j
            unsigned mm =
                  (unsigned)(a0.x == wm)        | ((unsigned)(a0.y == wm) << 1)
                | ((unsigned)(a0.z == wm) << 2) | ((unsigned)(a0.w == wm) << 3)
                | ((unsigned)(a1.x == wm) << 4) | ((unsigned)(a1.y == wm) << 5)
                | ((unsigned)(a1.z == wm) << 6) | ((unsigned)(a1.w == wm) << 7)
                | ((unsigned)(a2.x == wm) << 8) | ((unsigned)(a2.y == wm) << 9)
                | ((unsigned)(a2.z == wm) <<10) | ((unsigned)(a2.w == wm) <<11);
            unsigned lcnt = (unsigned)__popc(mm);
            unsigned lidx = 0x7fffffffu;
            if (mm) {
                int bit = __ffs(mm) - 1;
                lidx = (unsigned)(4*t + ((bit >> 2) << 11) + (bit & 3));  // 2048 = 4*TPB
            }
            unsigned wcnt = __reduce_add_sync(0xffffffffu, lcnt);
            unsigned widx = __reduce_min_sync(0xffffffffu, lidx);
            if (lane == 0) {
                spmax[r*NW + warp] = wm;
                spcnt[r*NW + warp] = (int)wcnt;
                spidx[r*NW + warp] = (int)widx;
            }
        }

        __syncthreads();                 // everyone done reading tiles[stage]
        int sn = s + DEPTH;
        if (t == 0 && sn * RPS < nrows) {
            mbar_expect_tx(mb0 + 8*stage, STAGEB);
            bulk_ldg(sbase + stage*STAGEB, (const char*)conf + (grow0 + sn*RPS) * ROWB, STAGEB, mb0 + 8*stage);
        }
        if (++stage == DEPTH) { stage = 0; ph ^= 1; }
    }
    __syncthreads();

    // per-row combine -> REGISTERS (this CTA matches its own rows later)
    float rowm = -1.f; int rowc = 0, rowi = 0;
    if (t < nrows) {
#pragma unroll
        for (int w = 0; w < NW; w++) {
            float om = spmax[t*NW + w];
            if (om > rowm)       { rowm = om; rowc = spcnt[t*NW + w]; rowi = spidx[t*NW + w]; }
            else if (om == rowm) { rowc += spcnt[t*NW + w]; rowi = min(rowi, spidx[t*NW + w]); }
        }
    }

    // flush privatized column-max partials (coalesced float4 stores)
    {
        float4* cp = (float4*)&g_colpart[((size_t)b * NN + n) * SS] + t;
        cp[0]     = z0;
        cp[TPB]   = z1;
        if (tail) cp[2*TPB] = z2;
    }
    if (t == 0) s_nl = 0;

    grid_bar();   // ---- barrier 1: all colpart complete ----

    // ---------------- Phase 2: coalesced 37-way colmax fold ------------------
    {
        const int cid = n * CTAS_PER_N + b;            // 0..147
        const int idx = cid * COLS_PER_CTA + t;
        if (t < COLS_PER_CTA && idx < NN*SS) {
            int n2 = idx / SS, j2 = idx % SS;
            float mf = 0.f;
#pragma unroll
            for (int b2 = 0; b2 < CTAS_PER_N; b2++)
                mf = fmaxf(mf, g_colpart[((size_t)b2 * NN + n2) * SS + j2]);
            g_colmax[idx] = mf;
        }
    }

    grid_bar();   // ---- barrier 2: all colmax complete ----

    // ---------------- Phase 3: match this CTA's own rows ---------------------
    {
        float mconf = 0.f; int jid = 0; float mv = 0.f;
        bool need = false;
        if (t < nrows) {
            const int i = rstart + t;                   // row within batch n
            const int r0 = i / W0, c0 = i % W0;
            const bool v0 = (r0 >= BR) & (r0 < H0 - BR) & (c0 >= BR) & (c0 < W0 - BR);
            if (v0 && rowm > THRV) {
                // rowi = global min-index of the row max; if it passes the mask
                // it is the first True regardless of ties.
                if (valid1(rowi) && g_colmax[n * SS + rowi] == rowm) {
                    mv = 1.f; jid = rowi; mconf = rowm;
                } else if (rowc > 1) {
                    need = true;     // a later tied position may pass -> rescan
                }
            }
        }
        if (need) { int p = atomicAdd(&s_nl, 1); s_list[p] = t; s_m[t] = rowm; }
        __syncthreads();
        if (t < nrows && !need) {
            const size_t gw = grow0 + t;
            out[gw]        = mconf;
            out[NL + gw]   = mv;
            out[2*NL + gw] = (float)jid;
        }

        const int nl = s_nl;
        for (int w = 0; w < nl; w++) {
            const int lrow = s_list[w];
            const float mm = s_m[lrow];
            const float* rowp = conf + (grow0 + lrow) * SS;
            if (t == 0) s_best = 0x7fffffffu;
            __syncthreads();
            // preload ALL chunks first (forces MLP=10), then test
            float vv[RESCAN_K];
#pragma unroll
            for (int k = 0; k < RESCAN_K; k++) {
                int j = t + k * TPB;
                vv[k] = (j < SS) ? rowp[j] : -1.f;
            }
            unsigned lb = 0x7fffffffu;
#pragma unroll
            for (int k = 0; k < RESCAN_K; k++) {
                int j = t + k * TPB;
                if (j < SS && vv[k] == mm && valid1(j) && g_colmax[n * SS + j] == vv[k])
                    lb = min(lb, (unsigned)j);
            }
            if (lb != 0x7fffffffu) atomicMin(&s_best, lb);
            __syncthreads();
            if (t == 0) {
                unsigned bsel = s_best;
                bool hit = (bsel != 0x7fffffffu);
                const size_t gw = grow0 + lrow;
                out[gw]        = hit ? mm : 0.f;
                out[NL + gw]   = hit ? 1.f : 0.f;
                out[2*NL + gw] = hit ? (float)bsel : 0.f;
            }
            __syncthreads();
        }
    }
}

extern "C" void kernel_launch(void* const* d_in, const int* in_sizes, int n_in,
                              void* d_out, int out_size) {
    const float* conf = (const float*)d_in[0];
    float* out = (float*)d_out;

    cudaFuncSetAttribute(fused, cudaFuncAttributeMaxDynamicSharedMemorySize, SMEM_REQ);
    dim3 g1(CTAS_PER_N, NN);          // 37 x 4 = 148 CTAs = exactly 1 per SM
    fused<<<g1, TPB, SMEM_REQ>>>(conf, out);
}